// round 12
// baseline (speedup 1.0000x reference)
#include <cuda_runtime.h>
#include <cuda_bf16.h>
#include <math.h>
#include <stdint.h>

// Problem constants (fixed shapes per reference)
#define N_NODES 100000
#define N_EDGES 1600000
#define F_IN    256
#define F_OUT   128
#define ALPHA   0.2f

// ---------------- device scratch (static; no allocation allowed) ----------------
__device__ __align__(16) float g_h[(size_t)N_NODES * F_OUT];   // 51.2 MB: h = x @ W
__device__ float g_sl[N_NODES];
__device__ float g_sr[N_NODES];
__device__ int   g_deg[N_NODES];
__device__ int   g_off[N_NODES + 1];
__device__ int   g_cur[N_NODES];
__device__ int   g_src[N_EDGES];
__device__ int   g_is64;
// W decomposed into bf16 limbs, TRANSPOSED to [n][k] so B acts col-major for mma row.col
__device__ __align__(16) __nv_bfloat16 g_wh[F_OUT * F_IN];
__device__ __align__(16) __nv_bfloat16 g_wl[F_OUT * F_IN];

// ---------------- warp reduction helpers ----------------
__device__ __forceinline__ float warpMax(float v) {
#pragma unroll
    for (int o = 16; o > 0; o >>= 1) v = fmaxf(v, __shfl_xor_sync(0xffffffffu, v, o));
    return v;
}
__device__ __forceinline__ float warpSum(float v) {
#pragma unroll
    for (int o = 16; o > 0; o >>= 1) v += __shfl_xor_sync(0xffffffffu, v, o);
    return v;
}

// ---------------- mma.sync / ldmatrix wrappers (standard PTX, compute_103-safe) ----------------
__device__ __forceinline__ void ldm_x4(uint32_t& r0, uint32_t& r1, uint32_t& r2, uint32_t& r3,
                                       uint32_t addr) {
    asm volatile("ldmatrix.sync.aligned.m8n8.x4.shared.b16 {%0,%1,%2,%3}, [%4];"
                 : "=r"(r0), "=r"(r1), "=r"(r2), "=r"(r3) : "r"(addr));
}
__device__ __forceinline__ void mma16816(float* c, const uint32_t* a, const uint32_t* b) {
    asm volatile("mma.sync.aligned.m16n8k16.row.col.f32.bf16.bf16.f32 "
                 "{%0,%1,%2,%3}, {%4,%5,%6,%7}, {%8,%9}, {%0,%1,%2,%3};"
                 : "+f"(c[0]), "+f"(c[1]), "+f"(c[2]), "+f"(c[3])
                 : "r"(a[0]), "r"(a[1]), "r"(a[2]), "r"(a[3]), "r"(b[0]), "r"(b[1]));
}
// pack two floats into a bf16x2 word: a -> low 16 bits, b -> high 16 bits
__device__ __forceinline__ uint32_t pack_bf16(float a, float b) {
    __nv_bfloat162 t(__float2bfloat16(a), __float2bfloat16(b));
    return *(uint32_t*)&t;
}

// ---------------- 0) edge dtype detection ----------------
__global__ void detect_kernel(const int* __restrict__ p) {
    int lane = threadIdx.x;
    int bad = 0;
    for (int k = lane; k < 256; k += 32)
        if (p[2 * k + 1] != 0) bad = 1;
    unsigned b = __ballot_sync(0xffffffffu, bad);
    if (lane == 0) g_is64 = (b == 0) ? 1 : 0;
}
__device__ __forceinline__ int edge_at(const void* eidx, long long elem) {
    if (g_is64) return (int)((const long long*)eidx)[elem];
    return ((const int*)eidx)[elem];
}

// ---------------- 0b) W -> transposed bf16 limbs ----------------
__global__ void convert_w_kernel(const float* __restrict__ w) {
    int nn = blockIdx.x;    // 0..127 (output feature)
    int k  = threadIdx.x;   // 0..255
    float v = w[(size_t)k * F_OUT + nn];
    __nv_bfloat16 hi = __float2bfloat16(v);
    float lo = v - __bfloat162float(hi);
    g_wh[nn * F_IN + k] = hi;
    g_wl[nn * F_IN + k] = __float2bfloat16(lo);
}

// ---------------- 1) mma.sync bf16-split GEMM: h = x @ W (+ fused scores) ----------------
// CTA tile 128x128, 8 warps: warp_m = wid&3 (rows of 32), warp_n = wid>>2 (cols of 64).
// K staged in 4 chunks of 64. Smem rows padded to 72 bf16 (144B = 16*9: ldmatrix 16B-aligned,
// 8 ldmatrix rows hit disjoint bank words -> conflict-free).
#define SROW   144                        // bytes per smem row
#define SA_H   0
#define SA_L   18432
#define SB_H   36864
#define SB_L   55296
#define SM_GEMM_TOTAL 73728

__global__ __launch_bounds__(256) void gemm_mma_kernel(
    const float* __restrict__ x,
    const float* __restrict__ a_l, const float* __restrict__ a_r, int n)
{
    extern __shared__ __align__(16) char smem[];
    const uint32_t sbase = (uint32_t)__cvta_generic_to_shared(smem);
    const int tid  = threadIdx.x;
    const int wid  = tid >> 5;
    const int lane = tid & 31;
    const int warp_m = wid & 3;    // 0..3 -> row block of 32
    const int warp_n = wid >> 2;   // 0..1 -> col block of 64
    const int rowBase = blockIdx.x * 128;

    float acc[2][8][4];
#pragma unroll
    for (int mt = 0; mt < 2; mt++)
#pragma unroll
        for (int nt = 0; nt < 8; nt++)
#pragma unroll
            for (int i = 0; i < 4; i++) acc[mt][nt][i] = 0.f;

    // per-lane ldmatrix base offsets
    const uint32_t aOff = sbase +
        (uint32_t)((warp_m * 32 + (lane & 15)) * SROW + (((lane >> 4) & 1) * 8) * 2);
    const uint32_t bOff = sbase +
        (uint32_t)((warp_n * 64 + ((lane >> 4) & 1) * 8 + (lane & 7)) * SROW
                   + (((lane >> 3) & 1) * 8) * 2);

    for (int kc = 0; kc < 4; kc++) {
        // ---- stage A chunk (fp32 -> bf16 hi/lo limbs), rows x k[kc*64,+64) ----
#pragma unroll
        for (int it = 0; it < 8; it++) {
            int idx = tid + it * 256;      // 0..2047 float4
            int r = idx >> 4;              // row 0..127
            int q = idx & 15;              // k-quad
            float4 v = make_float4(0.f, 0.f, 0.f, 0.f);
            int gr = rowBase + r;
            if (gr < n)
                v = *(const float4*)(x + (size_t)gr * F_IN + kc * 64 + q * 4);
            float hx = __bfloat162float(__float2bfloat16(v.x));
            float hy = __bfloat162float(__float2bfloat16(v.y));
            float hz = __bfloat162float(__float2bfloat16(v.z));
            float hw = __bfloat162float(__float2bfloat16(v.w));
            uint2 hi = make_uint2(pack_bf16(hx, hy), pack_bf16(hz, hw));
            uint2 lo = make_uint2(pack_bf16(v.x - hx, v.y - hy),
                                  pack_bf16(v.z - hz, v.w - hw));
            *(uint2*)(smem + SA_H + r * SROW + q * 8) = hi;
            *(uint2*)(smem + SA_L + r * SROW + q * 8) = lo;
        }
        // ---- stage B chunk (precomputed limbs), [n=128][k 64) ----
#pragma unroll
        for (int it = 0; it < 4; it++) {
            int idx = tid + it * 256;      // 0..1023 uint4
            int r = idx >> 3;              // n row 0..127
            int q = idx & 7;               // 8-bf16 group
            *(uint4*)(smem + SB_H + r * SROW + q * 16) =
                *(const uint4*)(g_wh + r * F_IN + kc * 64 + q * 8);
            *(uint4*)(smem + SB_L + r * SROW + q * 16) =
                *(const uint4*)(g_wl + r * F_IN + kc * 64 + q * 8);
        }
        __syncthreads();

        // ---- mma over 4 k16-steps ----
#pragma unroll
        for (int ks = 0; ks < 4; ks++) {
            uint32_t aH[2][4], aL[2][4], bH[4][4], bL[4][4];
#pragma unroll
            for (int mt = 0; mt < 2; mt++) {
                uint32_t ad = aOff + (uint32_t)(mt * 16 * SROW + ks * 32);
                ldm_x4(aH[mt][0], aH[mt][1], aH[mt][2], aH[mt][3], ad + SA_H);
                ldm_x4(aL[mt][0], aL[mt][1], aL[mt][2], aL[mt][3], ad + SA_L);
            }
#pragma unroll
            for (int p = 0; p < 4; p++) {
                uint32_t bd = bOff + (uint32_t)(p * 16 * SROW + ks * 32);
                ldm_x4(bH[p][0], bH[p][1], bH[p][2], bH[p][3], bd + SB_H);
                ldm_x4(bL[p][0], bL[p][1], bL[p][2], bL[p][3], bd + SB_L);
            }
#pragma unroll
            for (int mt = 0; mt < 2; mt++)
#pragma unroll
                for (int nt = 0; nt < 8; nt++) {
                    const int p = nt >> 1, hf = (nt & 1) * 2;
                    mma16816(acc[mt][nt], aH[mt], &bH[p][hf]);
                    mma16816(acc[mt][nt], aH[mt], &bL[p][hf]);
                    mma16816(acc[mt][nt], aL[mt], &bH[p][hf]);
                }
        }
        __syncthreads();
    }

    // ---- epilogue: store h + fused scores ----
    float* s_pl = (float*)smem;            // [128]
    float* s_pr = s_pl + 128;              // [128]
    ((float*)smem)[tid] = 0.f;             // zero both arrays (256 floats)
    __syncthreads();

    const int qrow = lane >> 2;            // 0..7
    const int qcol = 2 * (lane & 3);       // 0,2,4,6
#pragma unroll
    for (int mt = 0; mt < 2; mt++) {
        const int lr0 = warp_m * 32 + mt * 16 + qrow;   // local row of c0/c1
        const int lr1 = lr0 + 8;                         // local row of c2/c3
        const int gr0 = rowBase + lr0;
        const int gr1 = rowBase + lr1;
        float plA = 0.f, prA = 0.f, plB = 0.f, prB = 0.f;
#pragma unroll
        for (int nt = 0; nt < 8; nt++) {
            const int col = warp_n * 64 + nt * 8 + qcol;
            const float c0 = acc[mt][nt][0], c1 = acc[mt][nt][1];
            const float c2 = acc[mt][nt][2], c3 = acc[mt][nt][3];
            const float al0 = __ldg(a_l + col), al1 = __ldg(a_l + col + 1);
            const float ar0 = __ldg(a_r + col), ar1 = __ldg(a_r + col + 1);
            plA += c0 * al0 + c1 * al1;  prA += c0 * ar0 + c1 * ar1;
            plB += c2 * al0 + c3 * al1;  prB += c2 * ar0 + c3 * ar1;
            if (gr0 < n) *(float2*)(g_h + (size_t)gr0 * F_OUT + col) = make_float2(c0, c1);
            if (gr1 < n) *(float2*)(g_h + (size_t)gr1 * F_OUT + col) = make_float2(c2, c3);
        }
        // reduce over the 4 lanes of the quad (same row)
#pragma unroll
        for (int o = 1; o < 4; o <<= 1) {
            plA += __shfl_xor_sync(0xffffffffu, plA, o);
            prA += __shfl_xor_sync(0xffffffffu, prA, o);
            plB += __shfl_xor_sync(0xffffffffu, plB, o);
            prB += __shfl_xor_sync(0xffffffffu, prB, o);
        }
        if ((lane & 3) == 0) {
            atomicAdd(&s_pl[lr0], plA);  atomicAdd(&s_pr[lr0], prA);
            atomicAdd(&s_pl[lr1], plB);  atomicAdd(&s_pr[lr1], prB);
        }
    }
    __syncthreads();
    if (tid < 128) {
        int gr = rowBase + tid;
        if (gr < n) { g_sl[gr] = s_pl[tid]; g_sr[gr] = s_pr[tid]; }
    }
}

// ---------------- 2) CSR build ----------------
__global__ void zero_deg_kernel(int n) {
    int i = blockIdx.x * blockDim.x + threadIdx.x;
    if (i < n) g_deg[i] = 0;
}
__global__ void hist_kernel(const void* __restrict__ eidx, int e) {
    int i = blockIdx.x * blockDim.x + threadIdx.x;
    if (i < e) atomicAdd(&g_deg[edge_at(eidx, i)], 1);
}
__global__ __launch_bounds__(1024) void scan_kernel(int n) {
    __shared__ int sh_warp[32];
    __shared__ int sh_total;
    const int tid  = threadIdx.x;
    const int lane = tid & 31;
    const int wid  = tid >> 5;
    int running = 0;
    for (int base = 0; base < n; base += 1024) {
        int i = base + tid;
        int v = (i < n) ? g_deg[i] : 0;
        int incl = v;
#pragma unroll
        for (int o = 1; o < 32; o <<= 1) {
            int t = __shfl_up_sync(0xffffffffu, incl, o);
            if (lane >= o) incl += t;
        }
        if (lane == 31) sh_warp[wid] = incl;
        __syncthreads();
        if (tid < 32) {
            int ws = sh_warp[tid];
            int wi = ws;
#pragma unroll
            for (int o = 1; o < 32; o <<= 1) {
                int t = __shfl_up_sync(0xffffffffu, wi, o);
                if (tid >= o) wi += t;
            }
            sh_warp[tid] = wi - ws;
        }
        __syncthreads();
        int excl = incl - v + sh_warp[wid];
        if (i < n) { g_off[i] = running + excl; g_cur[i] = running + excl; }
        if (tid == 1023) sh_total = excl + v;
        __syncthreads();
        running += sh_total;
        __syncthreads();
    }
    if (tid == 0) g_off[n] = running;
}
__global__ void fill_kernel(const void* __restrict__ eidx, int e) {
    int i = blockIdx.x * blockDim.x + threadIdx.x;
    if (i < e) {
        int r = edge_at(eidx, i);
        int c = edge_at(eidx, (long long)e + i);
        int p = atomicAdd(&g_cur[r], 1);
        g_src[p] = c;
    }
}

// ---------------- 3) fused softmax + SpMM + bias + gated encoder ----------------
__global__ __launch_bounds__(256) void aggregate_kernel(
    const float* __restrict__ bias, const float* __restrict__ fc,
    const float* __restrict__ bf, float* __restrict__ out, int n)
{
    const int node = (blockIdx.x * blockDim.x + threadIdx.x) >> 5;
    const int lane = threadIdx.x & 31;
    if (node >= n) return;

    const int s = g_off[node];
    const int e = g_off[node + 1];
    const float sl = g_sl[node];

    float m = -INFINITY;
    for (int j = s + lane; j < e; j += 32) {
        int c = g_src[j];
        float v = sl + g_sr[c];
        v = v > 0.f ? v : ALPHA * v;
        m = fmaxf(m, v);
    }
    m = warpMax(m);

    float sum = 0.f;
    for (int j = s + lane; j < e; j += 32) {
        int c = g_src[j];
        float v = sl + g_sr[c];
        v = v > 0.f ? v : ALPHA * v;
        sum += __expf(v - m);
    }
    sum = warpSum(sum);
    const float inv = 1.f / (sum + 1e-16f);

    float4 acc = make_float4(0.f, 0.f, 0.f, 0.f);
    for (int j0 = s; j0 < e; j0 += 32) {
        int   j = j0 + lane;
        int   c = 0;
        float w = 0.f;
        if (j < e) {
            c = g_src[j];
            float v = sl + g_sr[c];
            v = v > 0.f ? v : ALPHA * v;
            w = __expf(v - m) * inv;
        }
        int cnt = min(32, e - j0);
        for (int t = 0; t < cnt; t++) {
            int   cc = __shfl_sync(0xffffffffu, c, t);
            float ww = __shfl_sync(0xffffffffu, w, t);
            const float4 hv = *(const float4*)(g_h + (size_t)cc * F_OUT + lane * 4);
            acc.x += ww * hv.x;
            acc.y += ww * hv.y;
            acc.z += ww * hv.z;
            acc.w += ww * hv.w;
        }
    }

    float4 bsv = *(const float4*)(bias + lane * 4);
    float4 v = make_float4(acc.x + bsv.x, acc.y + bsv.y, acc.z + bsv.z, acc.w + bsv.w);
    float4 fv = *(const float4*)(fc + lane * 4);
    float p = v.x * fv.x + v.y * fv.y + v.z * fv.z + v.w * fv.w;
    p = warpSum(p) + bf[0];
    float gate = 1.f / (1.f + __expf(-p));

    float4 o;
    o.x = (v.x < 0.f ? 0.f : v.x) + gate * (v.x > 0.f ? 0.f : v.x);
    o.y = (v.y < 0.f ? 0.f : v.y) + gate * (v.y > 0.f ? 0.f : v.y);
    o.z = (v.z < 0.f ? 0.f : v.z) + gate * (v.z > 0.f ? 0.f : v.z);
    o.w = (v.w < 0.f ? 0.f : v.w) + gate * (v.w > 0.f ? 0.f : v.w);
    *(float4*)(out + (size_t)node * F_OUT + lane * 4) = o;
}

// ---------------- launch ----------------
extern "C" void kernel_launch(void* const* d_in, const int* in_sizes, int n_in,
                              void* d_out, int out_size)
{
    const float* x      = (const float*)d_in[0];
    const void*  eidx   = d_in[1];               // [2, E]; int32 or int64 (detected)
    const float* weight = (const float*)d_in[3];
    const float* bias   = (const float*)d_in[4];
    const float* a_l    = (const float*)d_in[5];
    const float* a_r    = (const float*)d_in[6];
    const float* fc     = (const float*)d_in[7];
    const float* bf     = (const float*)d_in[8];
    float*       out    = (float*)d_out;

    const int n = in_sizes[0] / F_IN;    // 100000
    const int e = in_sizes[1] / 2;       // 1600000

    cudaFuncSetAttribute(gemm_mma_kernel,
                         cudaFuncAttributeMaxDynamicSharedMemorySize, SM_GEMM_TOTAL);

    detect_kernel<<<1, 32>>>((const int*)eidx);
    convert_w_kernel<<<F_OUT, F_IN>>>(weight);
    gemm_mma_kernel<<<(n + 127) / 128, 256, SM_GEMM_TOTAL>>>(x, a_l, a_r, n);
    zero_deg_kernel<<<(n + 255) / 256, 256>>>(n);
    hist_kernel<<<(e + 255) / 256, 256>>>(eidx, e);
    scan_kernel<<<1, 1024>>>(n);
    fill_kernel<<<(e + 255) / 256, 256>>>(eidx, e);
    aggregate_kernel<<<(n + 7) / 8, 256>>>(bias, fc, bf, out, n);
}